// round 17
// baseline (speedup 1.0000x reference)
#include <cuda_runtime.h>
#include <cuda_fp16.h>
#include <cstdint>

#define NGROUPS 512   // B*S/16
#define NSLOTS  64    // E*Sets
#define DDIM    512
#define TTOK    16
#define FDIM    32

typedef unsigned long long ull;

__device__ int g_winners[NGROUPS * NSLOTS];

// ---------------------------------------------------------------------------
// fp16 helpers
// ---------------------------------------------------------------------------
__device__ __forceinline__ uint32_t f16pair(float v0, float v1) {
    uint32_t r;
    asm("cvt.rn.f16x2.f32 %0, %1, %2;" : "=r"(r) : "f"(v1), "f"(v0));
    return r;
}
// split (v0,v1): low32 = fp16 hi-pair, high32 = fp16 residual-pair
__device__ __forceinline__ ull splitpack16(float v0, float v1) {
    const uint32_t h = f16pair(v0, v1);
    __half2 hh = *(const __half2*)&h;
    const float2 back = __half22float2(hh);
    const uint32_t l = f16pair(v0 - back.x, v1 - back.y);
    return (ull)h | ((ull)l << 32);
}
__device__ __forceinline__ void mma16(float* c, uint32_t a0, uint32_t a1,
                                      uint32_t a2, uint32_t a3,
                                      uint32_t b0, uint32_t b1) {
    asm volatile("mma.sync.aligned.m16n8k16.row.col.f32.f16.f16.f32 "
                 "{%0,%1,%2,%3}, {%4,%5,%6,%7}, {%8,%9}, {%0,%1,%2,%3};"
                 : "+f"(c[0]), "+f"(c[1]), "+f"(c[2]), "+f"(c[3])
                 : "r"(a0), "r"(a1), "r"(a2), "r"(a3), "r"(b0), "r"(b1));
}
__device__ __forceinline__ uint32_t ulo(ull v) { return (uint32_t)v; }
__device__ __forceinline__ uint32_t uhi(ull v) { return (uint32_t)(v >> 32); }

// ---------------------------------------------------------------------------
// Kernel 1: routing via 3-term split-fp16 mma. CTA = 2 contiguous groups
// (M=32 tokens), N=64 slots, K=512 — 256 CTAs for full SM coverage and a
// halved per-CTA critical path vs R16. Identical per-(group,slot) arithmetic
// => identical winners. Proven argmax + coop fp64 recheck. Zero-inits out.
// Smem: ls 2*64*17 f32 @0 (8704); Bu [2][32][68] ull @8704 (34816);
//       Xu [2][32][36] ull @43520 (18432). Total 61952.
// ---------------------------------------------------------------------------
#define ROFF_LS 0
#define ROFF_B  8704
#define ROFF_X  43520
#define RSMEM   61952

__global__ __launch_bounds__(256) void k_route_mma(const float* __restrict__ x,
                                                   const float* __restrict__ ctrl,
                                                   float* __restrict__ out)
{
    extern __shared__ __align__(16) char smraw[];
    float* ls = (float*)(smraw + ROFF_LS);
    ull*   Bb = (ull*)(smraw + ROFF_B);
    ull*   Xb = (ull*)(smraw + ROFF_X);
    __shared__ int sflags[128];
    __shared__ int swin[128];
    __shared__ int snf;
    __shared__ double dred[256];
    __shared__ double dlog[16];

    const int g0   = blockIdx.x * 2;      // 2 groups per CTA
    const int tid  = threadIdx.x;
    const int wid  = tid >> 5;
    const int lane = tid & 31;
    const int gq   = lane >> 2;
    const int c4   = lane & 3;
    const int mt   = wid & 1;             // m-tile == group within CTA
    const int nq   = wid >> 1;            // slot quarter (16 slots)
    const int m0   = mt * 16;

    if (tid == 0) snf = 0;

    // zero-init output tile (2 groups x 16 x 512)
    {
        float4* dst = (float4*)(out + (size_t)g0 * TTOK * DDIM);
        const float4 z4 = make_float4(0.f, 0.f, 0.f, 0.f);
        for (int i = tid; i < 4096; i += 256) dst[i] = z4;
    }

    const float* xbase = x + (size_t)g0 * TTOK * DDIM;   // 32 contiguous rows

    // staging maps
    const int xr = tid >> 3;             // row 0..31
    const int xc = tid & 7;              // word-class; words xc + 8i
    const int bkp = tid >> 3;            // ctrl k-pair 0..31
    const int bf0 = (tid & 7) * 8;       // 8 slots

    // ---- prefetch chunk 0
    float2 xv[4];
    float4 c0a, c0b, c1a, c1b;
    #pragma unroll
    for (int i = 0; i < 4; ++i)
        xv[i] = __ldg((const float2*)(xbase + xr * DDIM + 2 * (xc + 8 * i)));
    {
        const float* r0 = ctrl + (size_t)(2 * bkp) * 64 + bf0;
        const float* r1 = ctrl + (size_t)(2 * bkp + 1) * 64 + bf0;
        c0a = __ldg((const float4*)r0); c0b = __ldg((const float4*)(r0 + 4));
        c1a = __ldg((const float4*)r1); c1b = __ldg((const float4*)(r1 + 4));
    }
    // stage chunk 0 into buf 0
    {
        #pragma unroll
        for (int i = 0; i < 4; ++i)
            Xb[xr * 36 + xc + 8 * i] = splitpack16(xv[i].x, xv[i].y);
        #pragma unroll
        for (int e = 0; e < 4; ++e) {
            Bb[bkp * 68 + bf0 + e]     = splitpack16(((const float*)&c0a)[e],
                                                     ((const float*)&c1a)[e]);
            Bb[bkp * 68 + bf0 + 4 + e] = splitpack16(((const float*)&c0b)[e],
                                                     ((const float*)&c1b)[e]);
        }
    }
    __syncthreads();

    float acc1[2][4];
    #pragma unroll
    for (int j = 0; j < 2; ++j)
        #pragma unroll
        for (int e = 0; e < 4; ++e) acc1[j][e] = 0.f;

    // ---- main loop: logits[32,64] = X[32,512] @ ctrl[512,64]
    for (int cb = 0; cb < 8; ++cb) {
        if (cb < 7) {
            const int kb = (cb + 1) * 64;
            #pragma unroll
            for (int i = 0; i < 4; ++i)
                xv[i] = __ldg((const float2*)(xbase + xr * DDIM + kb + 2 * (xc + 8 * i)));
            const float* r0 = ctrl + (size_t)(kb + 2 * bkp) * 64 + bf0;
            const float* r1 = ctrl + (size_t)(kb + 2 * bkp + 1) * 64 + bf0;
            c0a = __ldg((const float4*)r0); c0b = __ldg((const float4*)(r0 + 4));
            c1a = __ldg((const float4*)r1); c1b = __ldg((const float4*)(r1 + 4));
        }

        const ull* Xu = Xb + (cb & 1) * 1152;
        const ull* Bu = Bb + (cb & 1) * 2176;
        #pragma unroll
        for (int s = 0; s < 4; ++s) {
            const int kp = s * 8 + c4;
            const ull a0 = Xu[(m0 + gq) * 36 + kp];
            const ull a1 = Xu[(m0 + 8 + gq) * 36 + kp];
            const ull a2 = Xu[(m0 + gq) * 36 + kp + 4];
            const ull a3 = Xu[(m0 + 8 + gq) * 36 + kp + 4];
            #pragma unroll
            for (int j = 0; j < 2; ++j) {
                const int n0 = nq * 16 + j * 8;
                const ull W1 = Bu[kp * 68 + n0 + gq];
                const ull W2 = Bu[(kp + 4) * 68 + n0 + gq];
                mma16(acc1[j], ulo(a0), ulo(a1), ulo(a2), ulo(a3), ulo(W1), ulo(W2));
                mma16(acc1[j], ulo(a0), ulo(a1), ulo(a2), ulo(a3), uhi(W1), uhi(W2));
                mma16(acc1[j], uhi(a0), uhi(a1), uhi(a2), uhi(a3), ulo(W1), ulo(W2));
            }
        }

        if (cb < 7) {
            ull* Xu2 = Xb + ((cb + 1) & 1) * 1152;
            ull* Bu2 = Bb + ((cb + 1) & 1) * 2176;
            #pragma unroll
            for (int i = 0; i < 4; ++i)
                Xu2[xr * 36 + xc + 8 * i] = splitpack16(xv[i].x, xv[i].y);
            #pragma unroll
            for (int e = 0; e < 4; ++e) {
                Bu2[bkp * 68 + bf0 + e]     = splitpack16(((const float*)&c0a)[e],
                                                          ((const float*)&c1a)[e]);
                Bu2[bkp * 68 + bf0 + 4 + e] = splitpack16(((const float*)&c0b)[e],
                                                          ((const float*)&c1b)[e]);
            }
        }
        __syncthreads();
    }

    // ---- epilogue: logits + tie-breaker into ls[g][slot][token] (pad 17)
    {
        const float step = 1e-6f / 15.f;
        #pragma unroll
        for (int j = 0; j < 2; ++j) {
            #pragma unroll
            for (int e = 0; e < 4; ++e) {
                const int slot  = nq * 16 + j * 8 + 2 * c4 + (e & 1);
                const int token = gq + 8 * (e >> 1);
                ls[(mt * 64 + slot) * 17 + token] = acc1[j][e] + step * (float)token;
            }
        }
    }
    __syncthreads();

    // ---- argmax per (group, slot); flag near-ties
    if (tid < 128) {
        const float* lp = ls + tid * 17;
        float best = -3.4e38f, second = -3.4e38f;
        int bi = 0;
        #pragma unroll
        for (int t = 0; t < TTOK; ++t) {
            const float v = lp[t];
            if (v >= best) { second = best; best = v; bi = t; }
            else if (v > second) { second = v; }
        }
        swin[tid] = bi;
        if (best - second < 2e-5f) { int p = atomicAdd(&snf, 1); sflags[p] = tid; }
    }
    __syncthreads();

    // ---- cooperative fp64 recheck of flagged slots (rare)
    const int nf = snf;
    for (int i = 0; i < nf; ++i) {
        const int sfl = sflags[i];
        const int g2 = sfl >> 6, s2 = sfl & 63;
        const int t = tid >> 4, j = tid & 15;
        double a = 0.0;
        const float* xr2 = x + ((size_t)(g0 + g2) * TTOK + t) * DDIM + j * 32;
        const float* cp  = ctrl + (size_t)(j * 32) * 64 + s2;
        #pragma unroll 8
        for (int k = 0; k < 32; ++k)
            a += (double)__ldg(xr2 + k) * (double)__ldg(cp + (size_t)k * 64);
        dred[t * 16 + j] = a;
        __syncthreads();
        if (tid < 16) {
            double tot = 0.0;
            #pragma unroll
            for (int j2 = 0; j2 < 16; ++j2) tot += dred[tid * 16 + j2];
            dlog[tid] = tot + (double)tid * (1e-6 / 15.0);
        }
        __syncthreads();
        if (tid == 0) {
            double best = -1e300; int bi = 0;
            #pragma unroll
            for (int t2 = 0; t2 < TTOK; ++t2)
                if (dlog[t2] >= best) { best = dlog[t2]; bi = t2; }
            swin[sfl] = bi;
        }
        __syncthreads();
    }

    if (tid < 128)
        g_winners[(g0 + (tid >> 6)) * 64 + (tid & 63)] = swin[tid];
}

// ---------------------------------------------------------------------------
// Kernel 2: split-fp16 mma.sync expert (2-term), 256 thr / 8 warps, 128 rows.
// (byte-identical to R15/R16 — proven: 42.2us, rel_err 2.934e-4)
// ---------------------------------------------------------------------------
#define OFF_ROWB 0
#define OFF_B1   512
#define OFF_X    18944
#define SMEM2    59904

__global__ __launch_bounds__(256, 2) void k_expert(const float* __restrict__ x,
                                                   const float* __restrict__ f1,
                                                   const float* __restrict__ f2,
                                                   float* __restrict__ out)
{
    extern __shared__ __align__(16) char smraw[];
    int* rowb = (int*)(smraw + OFF_ROWB);
    ull* B1b  = (ull*)(smraw + OFF_B1);   // [2][32*36]
    ull* Xb   = (ull*)(smraw + OFF_X);    // [2][128*20]
    ull* B2b  = (ull*)(smraw + OFF_X);    // [2][8*132] alias

    const int slot = blockIdx.y;
    const int g0   = blockIdx.x * 128;
    const int tid  = threadIdx.x;
    const int wid  = tid >> 5;
    const int lane = tid & 31;
    const int gq   = lane >> 2;
    const int c4   = lane & 3;

    if (tid < 128) {
        const int gg = g0 + tid;
        rowb[tid] = (gg * TTOK + g_winners[gg * 64 + slot]) * DDIM;
    }
    __syncthreads();

    const int m0 = wid * 16;

    const int xr0 = tid >> 4;
    const int xP  = tid & 15;
    const int xkl = ((xP >> 2) << 3) | (xP & 3);
    const int bkp = tid >> 3;
    const int bf0 = (tid & 7) * 4;
    const float* f1b = f1 + slot * 32 + bf0;
    const int b2P  = tid >> 5;
    const int b2kl = ((b2P >> 2) << 3) | (b2P & 3);
    const int b2n  = (tid & 31) * 4;
    const float* f2b = f2 + (size_t)slot * (FDIM * DDIM) + b2n;

    float2 xa[8], xbv[8];
    float4 w0a, w1a;
    #pragma unroll
    for (int p = 0; p < 8; ++p) {
        const float* xp = x + rowb[xr0 + 16 * p] + 2 * xkl;
        xa[p]  = __ldg((const float2*)xp);
        xbv[p] = __ldg((const float2*)(xp + 8));
    }
    w0a = __ldg((const float4*)(f1b + (size_t)(2 * bkp) * 2048));
    w1a = __ldg((const float4*)(f1b + (size_t)(2 * bkp + 1) * 2048));

    {
        ull* Xu = Xb;
        #pragma unroll
        for (int p = 0; p < 8; ++p)
            Xu[(xr0 + 16 * p) * 20 + xP] =
                (ull)f16pair(xa[p].x, xa[p].y) | ((ull)f16pair(xbv[p].x, xbv[p].y) << 32);
        ull* B1u = B1b;
        const float* ka0 = (const float*)&w0a;
        const float* kb0 = (const float*)&w1a;
        #pragma unroll
        for (int e = 0; e < 4; e += 2) {
            ulonglong2 wa;
            wa.x = splitpack16(ka0[e],     kb0[e]);
            wa.y = splitpack16(ka0[e + 1], kb0[e + 1]);
            *(ulonglong2*)&B1u[bkp * 36 + bf0 + e] = wa;
        }
    }
    __syncthreads();

    float acc1[4][4];
    #pragma unroll
    for (int j = 0; j < 4; ++j)
        #pragma unroll
        for (int e = 0; e < 4; ++e) acc1[j][e] = 0.f;

    for (int cb = 0; cb < 8; ++cb) {
        if (cb < 7) {
            const int kb = (cb + 1) * 64;
            #pragma unroll
            for (int p = 0; p < 8; ++p) {
                const float* xp = x + rowb[xr0 + 16 * p] + kb + 2 * xkl;
                xa[p]  = __ldg((const float2*)xp);
                xbv[p] = __ldg((const float2*)(xp + 8));
            }
            w0a = __ldg((const float4*)(f1b + (size_t)(kb + 2 * bkp) * 2048));
            w1a = __ldg((const float4*)(f1b + (size_t)(kb + 2 * bkp + 1) * 2048));
        }

        const ull* Xu  = Xb  + (cb & 1) * 2560;
        const ull* B1u = B1b + (cb & 1) * 1152;
        #pragma unroll
        for (int s = 0; s < 4; ++s) {
            const ull a02 = Xu[(m0 + gq) * 20 + 4 * s + c4];
            const ull a13 = Xu[(m0 + 8 + gq) * 20 + 4 * s + c4];
            const int kp = 8 * s + c4;
            #pragma unroll
            for (int j = 0; j < 4; ++j) {
                const ull W1 = B1u[kp * 36 + j * 8 + gq];
                const ull W2 = B1u[(kp + 4) * 36 + j * 8 + gq];
                mma16(acc1[j], ulo(a02), ulo(a13), uhi(a02), uhi(a13), ulo(W1), ulo(W2));
                mma16(acc1[j], ulo(a02), ulo(a13), uhi(a02), uhi(a13), uhi(W1), uhi(W2));
            }
        }

        if (cb < 7) {
            ull* Xu2  = Xb  + ((cb + 1) & 1) * 2560;
            ull* B1u2 = B1b + ((cb + 1) & 1) * 1152;
            #pragma unroll
            for (int p = 0; p < 8; ++p)
                Xu2[(xr0 + 16 * p) * 20 + xP] =
                    (ull)f16pair(xa[p].x, xa[p].y) | ((ull)f16pair(xbv[p].x, xbv[p].y) << 32);
            const float* ka0 = (const float*)&w0a;
            const float* kb0 = (const float*)&w1a;
            #pragma unroll
            for (int e = 0; e < 4; e += 2) {
                ulonglong2 wa;
                wa.x = splitpack16(ka0[e],     kb0[e]);
                wa.y = splitpack16(ka0[e + 1], kb0[e + 1]);
                *(ulonglong2*)&B1u2[bkp * 36 + bf0 + e] = wa;
            }
        }
        __syncthreads();
    }

    uint32_t yh[2][4], yl[2][4];
    #pragma unroll
    for (int s = 0; s < 2; ++s) {
        const int j0 = 2 * s, j1 = 2 * s + 1;
        ull p;
        p = splitpack16(fmaxf(acc1[j0][0], 0.f), fmaxf(acc1[j0][1], 0.f));
        yh[s][0] = ulo(p); yl[s][0] = uhi(p);
        p = splitpack16(fmaxf(acc1[j0][2], 0.f), fmaxf(acc1[j0][3], 0.f));
        yh[s][1] = ulo(p); yl[s][1] = uhi(p);
        p = splitpack16(fmaxf(acc1[j1][0], 0.f), fmaxf(acc1[j1][1], 0.f));
        yh[s][2] = ulo(p); yl[s][2] = uhi(p);
        p = splitpack16(fmaxf(acc1[j1][2], 0.f), fmaxf(acc1[j1][3], 0.f));
        yh[s][3] = ulo(p); yl[s][3] = uhi(p);
    }

    const int ro0 = rowb[m0 + gq];
    const int ro1 = rowb[m0 + 8 + gq];

    float4 v0, v1, v2, v3;
    {
        const float* b = f2b;
        v0 = __ldg((const float4*)(b + (size_t)(2 * b2kl)     * DDIM));
        v1 = __ldg((const float4*)(b + (size_t)(2 * b2kl + 1) * DDIM));
        v2 = __ldg((const float4*)(b + (size_t)(2 * b2kl + 8) * DDIM));
        v3 = __ldg((const float4*)(b + (size_t)(2 * b2kl + 9) * DDIM));
    }

    {
        ull* B2u = B2b;
        const float* r0 = (const float*)&v0;
        const float* r1 = (const float*)&v1;
        const float* r2 = (const float*)&v2;
        const float* r3 = (const float*)&v3;
        #pragma unroll
        for (int e = 0; e < 4; e += 2) {
            ulonglong2 w;
            w.x = (ull)f16pair(r0[e],   r1[e])   | ((ull)f16pair(r2[e],   r3[e])   << 32);
            w.y = (ull)f16pair(r0[e+1], r1[e+1]) | ((ull)f16pair(r2[e+1], r3[e+1]) << 32);
            *(ulonglong2*)&B2u[b2P * 132 + b2n + e] = w;
        }
    }
    __syncthreads();

    for (int nc = 0; nc < 4; ++nc) {
        if (nc < 3) {
            const float* b = f2b + (nc + 1) * 128;
            v0 = __ldg((const float4*)(b + (size_t)(2 * b2kl)     * DDIM));
            v1 = __ldg((const float4*)(b + (size_t)(2 * b2kl + 1) * DDIM));
            v2 = __ldg((const float4*)(b + (size_t)(2 * b2kl + 8) * DDIM));
            v3 = __ldg((const float4*)(b + (size_t)(2 * b2kl + 9) * DDIM));
        }

        const ull* B2u = B2b + (nc & 1) * 1056;
        #pragma unroll 2
        for (int nt = 0; nt < 16; ++nt) {
            const int n0 = nt * 8;
            float acc[4] = {0.f, 0.f, 0.f, 0.f};
            #pragma unroll
            for (int s = 0; s < 2; ++s) {
                const ull W = B2u[(4 * s + c4) * 132 + n0 + gq];
                mma16(acc, yh[s][0], yh[s][1], yh[s][2], yh[s][3], ulo(W), uhi(W));
                mma16(acc, yl[s][0], yl[s][1], yl[s][2], yl[s][3], ulo(W), uhi(W));
            }
            const int d = nc * 128 + n0 + 2 * c4;
            atomicAdd((float2*)(out + ro0 + d), make_float2(acc[0], acc[1]));
            atomicAdd((float2*)(out + ro1 + d), make_float2(acc[2], acc[3]));
        }
        __syncthreads();

        if (nc < 3) {
            ull* B2u2 = B2b + ((nc + 1) & 1) * 1056;
            const float* r0 = (const float*)&v0;
            const float* r1 = (const float*)&v1;
            const float* r2 = (const float*)&v2;
            const float* r3 = (const float*)&v3;
            #pragma unroll
            for (int e = 0; e < 4; e += 2) {
                ulonglong2 w;
                w.x = (ull)f16pair(r0[e],   r1[e])   | ((ull)f16pair(r2[e],   r3[e])   << 32);
                w.y = (ull)f16pair(r0[e+1], r1[e+1]) | ((ull)f16pair(r2[e+1], r3[e+1]) << 32);
                *(ulonglong2*)&B2u2[b2P * 132 + b2n + e] = w;
            }
            __syncthreads();
        }
    }
}

// ---------------------------------------------------------------------------
extern "C" void kernel_launch(void* const* d_in, const int* in_sizes, int n_in,
                              void* d_out, int out_size)
{
    (void)in_sizes; (void)n_in; (void)out_size;
    const float* x    = (const float*)d_in[0];
    const float* ctrl = (const float*)d_in[1];
    const float* f1   = (const float*)d_in[2];
    const float* f2   = (const float*)d_in[3];
    float* out = (float*)d_out;

    cudaFuncSetAttribute(k_route_mma, cudaFuncAttributeMaxDynamicSharedMemorySize, RSMEM);
    cudaFuncSetAttribute(k_expert,    cudaFuncAttributeMaxDynamicSharedMemorySize, SMEM2);

    k_route_mma<<<NGROUPS / 2, 256, RSMEM>>>(x, ctrl, out);
    k_expert<<<dim3(4, 64), 256, SMEM2>>>(x, f1, f2, out);
}